// round 13
// baseline (speedup 1.0000x reference)
#include <cuda_runtime.h>
#include <cuda_bf16.h>
#include <cstdint>

// Problem constants
#define B_DIM 4
#define S_DIM 256
#define V_DIM 50257u
#define D_DIM 768
#define ROWS (B_DIM * S_DIM)     // 1024
#define D4 (D_DIM / 4)           // 192 float4 per output row
#define SPLIT 25128u             // front half [0,SPLIT), back half [SPLIT,V)
#define NTH 256
#define BATCH 2                  // float4 per thread per chunk -> 8KB chunks
#define CH (BATCH * NTH)         // 512 float4 per chunk

// Per-row early-exit flag (payload-free) and exit counter for self-cleaning.
// Invariant: both arrays are all-zero at every kernel launch. The second
// sibling to finish a row resets both, and only after both siblings have
// stopped touching them (last-to-arrive semantics), so graph replays are safe.
__device__ int g_flag[ROWS];
__device__ int g_cnt[ROWS];

__device__ __forceinline__ bool nz4(float4 v)
{
    return ((__float_as_uint(v.x) | __float_as_uint(v.y) |
             __float_as_uint(v.z) | __float_as_uint(v.w)) != 0u);
}

__global__ void __launch_bounds__(NTH)
half_scan_nowait_kernel(const float*  __restrict__ oh,
                        const float4* __restrict__ weight,
                        float4*       __restrict__ out)
{
    __shared__ int   s_col;
    __shared__ float s_val;
    __shared__ int   s_found;

    const unsigned int row  = blockIdx.x >> 1;
    const unsigned int half = blockIdx.x & 1u;
    const unsigned int tid  = threadIdx.x;

    if (tid == 0) s_found = 0;
    __syncthreads();

    // This block's flat element range [lo, hi).
    const unsigned int a  = row * V_DIM;
    const unsigned int lo = a + (half ? SPLIT : 0u);
    const unsigned int hi = a + (half ? V_DIM : SPLIT);

    const unsigned int first4 = (lo + 3u) & ~3u;
    const unsigned int b4s    = first4 >> 2;       // float4 idx, inclusive
    const unsigned int b4e    = hi >> 2;           // float4 idx, exclusive

    volatile int* vf = &s_found;
    volatile int* gf = &g_flag[row];

    // Record a found nonzero: block-shared payload + global flag.
    auto record = [&](float val, unsigned int flat) {
        s_col = (int)(flat - a);
        s_val = val;
        __threadfence_block();
        s_found = 1;
        *gf = 1;
        __threadfence();          // push flag toward L2 promptly (rare path)
    };

    // --- scalar head (<=3 elems) ---
    if (tid < 4u && lo + tid < first4) {
        float v = oh[lo + tid];
        if (v != 0.0f) record(v, lo + tid);
    }
    // --- scalar tail (<=3 elems) ---
    if (tid < 4u) {
        unsigned int e = (b4e << 2) + tid;
        if (e < hi) {
            float v = oh[e];
            if (v != 0.0f) record(v, e);
        }
    }

    // --- pipelined float4 body: predicate-free steady loop ---
    const float4* __restrict__ oh4 = (const float4*)oh;
    const float4 z4 = make_float4(0.f, 0.f, 0.f, 0.f);

    const unsigned int nfull = (b4e - b4s) / CH;   // complete chunks
    unsigned int i = b4s + tid;

    // prologue: load chunk 0 (unbounded only if it's a full chunk)
    float4 cur[BATCH];
    if (nfull > 0u) {
        #pragma unroll
        for (int k = 0; k < BATCH; ++k)
            cur[k] = __ldcs(&oh4[i + (unsigned int)k * NTH]);
    }

    unsigned int c = 0;
    for (; c < nfull; ++c) {
        int f = *vf | *gf;                      // LDS + L2 read, hide under LDGs

        float4 nxt[BATCH];
        if (c + 1u < nfull) {                   // uniform scalar branch
            #pragma unroll
            for (int k = 0; k < BATCH; ++k)
                nxt[k] = __ldcs(&oh4[i + CH + (unsigned int)k * NTH]);
        } else {
            #pragma unroll
            for (int k = 0; k < BATCH; ++k) nxt[k] = z4;
        }

        if (f) { i += CH; break; }              // someone found it: exit

        #pragma unroll
        for (int k = 0; k < BATCH; ++k) {
            if (nz4(cur[k])) {
                unsigned int fb = (i + (unsigned int)k * NTH) * 4u;
                float vals[4] = {cur[k].x, cur[k].y, cur[k].z, cur[k].w};
                #pragma unroll
                for (int l = 0; l < 4; ++l)
                    if (vals[l] != 0.0f) record(vals[l], fb + (unsigned int)l);
            }
        }

        #pragma unroll
        for (int k = 0; k < BATCH; ++k) cur[k] = nxt[k];
        i += CH;
    }

    // remainder (< one chunk), only if nothing found yet
    if (!(*vf) && !(*gf)) {
        for (unsigned int j = b4s + nfull * CH + tid; j < b4e; j += NTH) {
            float4 v = __ldcs(&oh4[j]);
            if (nz4(v)) {
                unsigned int fb = j * 4u;
                float vals[4] = {v.x, v.y, v.z, v.w};
                #pragma unroll
                for (int l = 0; l < 4; ++l)
                    if (vals[l] != 0.0f) record(vals[l], fb + (unsigned int)l);
            }
        }
    }

    __syncthreads();   // s_found / s_col / s_val coherent across block

    // --- finder gathers the WHOLE output row; non-finder does nothing ---
    if (s_found) {
        const int   col = s_col;
        const float s   = s_val;
        if (tid < D4) {
            float4 w = __ldg(&weight[(size_t)col * D4 + tid]);
            float4 o;
            o.x = s * w.x;
            o.y = s * w.y;
            o.z = s * w.z;
            o.w = s * w.w;
            out[(size_t)row * D4 + tid] = o;
        }
    }

    __syncthreads();   // block fully done with g_flag before signing off

    // --- self-cleaning exit: second sibling to arrive resets row state ---
    if (tid == 0) {
        int old = atomicAdd(&g_cnt[row], 1);
        if (old == 1) {           // last of the two: nobody reads flags anymore
            g_flag[row] = 0;
            g_cnt[row]  = 0;
        }
    }
}

// ---------------------------------------------------------------------------
// Launch: d_in[0] = one_hot [B,S,V] f32, d_in[1] = weight [V,D] f32.
// Output [B,S,D] f32. Two independent blocks per row, no cross-block waits.
// ---------------------------------------------------------------------------
extern "C" void kernel_launch(void* const* d_in, const int* in_sizes, int n_in,
                              void* d_out, int out_size)
{
    const float*  oh     = (const float*)d_in[0];
    const float4* weight = (const float4*)d_in[1];
    float4*       out    = (float4*)d_out;

    (void)in_sizes; (void)n_in; (void)out_size;

    half_scan_nowait_kernel<<<ROWS * 2, NTH>>>(oh, weight, out);
}

// round 15
// speedup vs baseline: 1.3076x; 1.3076x over previous
#include <cuda_runtime.h>
#include <cuda_bf16.h>
#include <cooperative_groups.h>
#include <cstdint>

namespace cg = cooperative_groups;

// Problem constants
#define B_DIM 4
#define S_DIM 256
#define V_DIM 50257u
#define D_DIM 768
#define ROWS (B_DIM * S_DIM)     // 1024
#define D4 (D_DIM / 4)           // 192 float4 per output row
#define SPLIT 25128u             // front half [0,SPLIT), back half [SPLIT,V)
#define NTH 256                  // threads per CTA; BATCH=1 -> 4KB chunks

// ---------------------------------------------------------------------------
// 2-CTA cluster per row: rank 0 scans the front half, rank 1 the back half.
// Early-exit flag lives in EACH CTA's own shared memory (LDS-speed poll);
// the finder sets its own flag and the peer's via DSMEM (one cross-CTA store
// on the rare path). The finder CTA alone (detected via s_col >= 0, set only
// by a local record) gathers the whole output row. No global state; final
// cluster.sync() covers DSMEM lifetime. Steady loop is predicate-free and
// software-pipelined (next chunk + next flag issued before the stale-flag
// branch). Skipping data after the flag is set is safe: one nonzero per row.
// ---------------------------------------------------------------------------
__device__ __forceinline__ bool nz4(float4 v)
{
    return ((__float_as_uint(v.x) | __float_as_uint(v.y) |
             __float_as_uint(v.z) | __float_as_uint(v.w)) != 0u);
}

__global__ void __launch_bounds__(NTH) __cluster_dims__(2, 1, 1)
row_cluster_scan_kernel(const float*  __restrict__ oh,
                        const float4* __restrict__ weight,
                        float4*       __restrict__ out)
{
    __shared__ int   s_flag;
    __shared__ int   s_col;
    __shared__ float s_val;

    cg::cluster_group cl = cg::this_cluster();

    const unsigned int row  = blockIdx.x >> 1;
    const unsigned int half = blockIdx.x & 1u;       // == cluster rank
    const unsigned int tid  = threadIdx.x;

    if (tid == 0) { s_flag = 0; s_col = -1; }
    __syncthreads();
    cl.sync();                    // both CTAs' flags initialized before any set

    int* peer_flag = cl.map_shared_rank(&s_flag, (int)(half ^ 1u));

    // This CTA's flat element range [lo, hi).
    const unsigned int a  = row * V_DIM;
    const unsigned int lo = a + (half ? SPLIT : 0u);
    const unsigned int hi = a + (half ? V_DIM : SPLIT);

    const unsigned int first4 = (lo + 3u) & ~3u;
    const unsigned int b4s    = first4 >> 2;         // float4 idx, inclusive
    const unsigned int b4e    = hi >> 2;             // float4 idx, exclusive

    volatile int* vflag = &s_flag;

    auto record = [&](float val, unsigned int flat) {
        s_col = (int)(flat - a);
        s_val = val;
        __threadfence_block();
        s_flag = 1;
        *peer_flag = 1;           // DSMEM store; peer polls its own smem
        __threadfence();
    };

    // --- scalar head (<=3 elems) ---
    if (tid < 4u && lo + tid < first4) {
        float v = oh[lo + tid];
        if (v != 0.0f) record(v, lo + tid);
    }
    // --- scalar tail (<=3 elems) ---
    if (tid < 4u) {
        unsigned int e = (b4e << 2) + tid;
        if (e < hi) {
            float v = oh[e];
            if (v != 0.0f) record(v, e);
        }
    }

    // --- float4 body: BATCH=1 pipelined chunks (4KB), predicate-free ---
    const float4* __restrict__ oh4 = (const float4*)oh;
    const unsigned int nfull = (b4e - b4s) / NTH;    // complete chunks
    unsigned int i = b4s + tid;

    int f = 0;
    if (nfull > 0u) {
        float4 cur = __ldcs(&oh4[i]);

        for (unsigned int c = 0; c + 1u < nfull; ++c) {
            int    fn  = *vflag;                 // LDS: for NEXT iteration
            float4 nxt = __ldcs(&oh4[i + NTH]);  // prefetch chunk c+1

            if (f) goto scan_done;               // stale by one chunk: safe

            if (nz4(cur)) {
                unsigned int fb = i * 4u;
                float vals[4] = {cur.x, cur.y, cur.z, cur.w};
                #pragma unroll
                for (int l = 0; l < 4; ++l)
                    if (vals[l] != 0.0f) record(vals[l], fb + (unsigned int)l);
            }

            cur = nxt;
            f   = fn;
            i  += NTH;
        }

        if (!f && nz4(cur)) {                    // last full chunk
            unsigned int fb = i * 4u;
            float vals[4] = {cur.x, cur.y, cur.z, cur.w};
            #pragma unroll
            for (int l = 0; l < 4; ++l)
                if (vals[l] != 0.0f) record(vals[l], fb + (unsigned int)l);
        }
        i += NTH;
    }

    // remainder (< one chunk)
    if (!*vflag) {
        for (unsigned int j = b4s + nfull * NTH + tid; j < b4e; j += NTH) {
            float4 v = __ldcs(&oh4[j]);
            if (nz4(v)) {
                unsigned int fb = j * 4u;
                float vals[4] = {v.x, v.y, v.z, v.w};
                #pragma unroll
                for (int l = 0; l < 4; ++l)
                    if (vals[l] != 0.0f) record(vals[l], fb + (unsigned int)l);
            }
        }
    }
scan_done:
    __syncthreads();   // s_col / s_val coherent across this CTA

    // --- finder CTA (s_col >= 0: record() ran locally) gathers whole row ---
    {
        int   col = s_col;
        float sv  = s_val;
        if (col >= 0 && tid < D4) {
            float4 w = __ldg(&weight[(size_t)col * D4 + tid]);
            float4 o;
            o.x = sv * w.x;
            o.y = sv * w.y;
            o.z = sv * w.z;
            o.w = sv * w.w;
            out[(size_t)row * D4 + tid] = o;
        }
    }

    cl.sync();         // DSMEM lifetime: no CTA exits while peer may store
}

extern "C" void kernel_launch(void* const* d_in, const int* in_sizes, int n_in,
                              void* d_out, int out_size)
{
    const float*  oh     = (const float*)d_in[0];
    const float4* weight = (const float4*)d_in[1];
    float4*       out    = (float4*)d_out;

    (void)in_sizes; (void)n_in; (void)out_size;

    row_cluster_scan_kernel<<<ROWS * 2, NTH>>>(oh, weight, out);
}